// round 8
// baseline (speedup 1.0000x reference)
#include <cuda_runtime.h>
#include <cuda_bf16.h>
#include <cstdint>
#include <cstddef>

#define NN   10000
#define NP   10048          // padding for the elementwise/mult kernels (157*64)
#define NPG  10112          // padding for the GEMM/topk (79*128)
#define DD   128
#define NCAND 32

// ---------------- device scratch ----------------
__device__ float g_xn[(size_t)NPG*DD];              // normalized fp32
__device__ __nv_bfloat16 g_xh[(size_t)NPG*DD];      // bf16 of normalized
__device__ float g_sim[(size_t)NPG*NPG];
__device__ int   g_cand[(size_t)NN*NCAND];
__device__ int   g_knn[(size_t)NN*16];
__device__ float g_mult[(size_t)2048*NP];           // [i][j][NP] per branch
__device__ float g_coef[(size_t)96*NP];             // [j][NP] per branch
__device__ float g_hyper[(size_t)NN*5*DD];

__device__ __forceinline__ unsigned long long kmax64(unsigned long long a, unsigned long long b){
    return a > b ? a : b;
}

// ---------------- normalize rows -> fp32 + bf16 ----------------
__global__ __launch_bounds__(256) void k_norm(const float* __restrict__ feats){
    int w = threadIdx.x >> 5, lane = threadIdx.x & 31;
    int row = blockIdx.x*8 + w;
    if (row >= NPG) return;
    float4 v = make_float4(0.f,0.f,0.f,0.f);
    if (row < NN){
        v = *(const float4*)(feats + (size_t)row*DD + lane*4);
        float ss = v.x*v.x + v.y*v.y + v.z*v.z + v.w*v.w;
        #pragma unroll
        for (int o=16;o;o>>=1) ss += __shfl_xor_sync(0xffffffffu, ss, o);
        float inv = 1.0f / fmaxf(sqrtf(ss), 1e-12f);
        v.x*=inv; v.y*=inv; v.z*=inv; v.w*=inv;
    }
    *(float4*)(g_xn + (size_t)row*DD + lane*4) = v;
    __nv_bfloat16 hi[4] = { __float2bfloat16_rn(v.x), __float2bfloat16_rn(v.y),
                            __float2bfloat16_rn(v.z), __float2bfloat16_rn(v.w) };
    *(uint2*)(g_xh + (size_t)row*DD + lane*4) = *(uint2*)hi;
}

// ---------------- approx sim = xh @ xh^T (single-pass bf16 HMMA) ----------
#define LDSM4(r0,r1,r2,r3,addr) \
    asm volatile("ldmatrix.sync.aligned.m8n8.x4.shared.b16 {%0,%1,%2,%3},[%4];" \
        : "=r"(r0),"=r"(r1),"=r"(r2),"=r"(r3) : "r"(addr))
#define LDSM2(r0,r1,addr) \
    asm volatile("ldmatrix.sync.aligned.m8n8.x2.shared.b16 {%0,%1},[%2];" \
        : "=r"(r0),"=r"(r1) : "r"(addr))
#define MMA16816(c,a,b) \
    asm volatile("mma.sync.aligned.m16n8k16.row.col.f32.bf16.bf16.f32 " \
        "{%0,%1,%2,%3},{%4,%5,%6,%7},{%8,%9},{%0,%1,%2,%3};" \
        : "+f"(c[0]),"+f"(c[1]),"+f"(c[2]),"+f"(c[3]) \
        : "r"(a[0]),"r"(a[1]),"r"(a[2]),"r"(a[3]),"r"(b[0]),"r"(b[1]))

#define SIM_SMEM (2*18432)
#define SROW 72          // smem row stride in bf16 (144 bytes, conflict-free ldmatrix)

__global__ __launch_bounds__(256) void k_simT(){
    extern __shared__ __align__(16) char smem[];
    char* sA = smem;
    char* sB = smem + 18432;

    const int tid  = threadIdx.x;
    const int wid  = tid >> 5;
    const int lane = tid & 31;
    const int bm = blockIdx.y, bn = blockIdx.x;
    const int warpM = (wid & 3) * 32;
    const int warpN = (wid >> 2) * 64;

    float c[2][8][4];
    #pragma unroll
    for (int t=0;t<2;t++)
        #pragma unroll
        for (int j=0;j<8;j++)
            #pragma unroll
            for (int q=0;q<4;q++) c[t][j][q] = 0.f;

    uint32_t aoff = (uint32_t)((warpM + (lane & 15))*SROW*2 + (lane >> 4)*16);
    uint32_t boff = (uint32_t)((warpN + (lane & 7))*SROW*2 + ((lane >> 3) & 1)*16);

    uint32_t sA_u = (uint32_t)__cvta_generic_to_shared(sA);
    uint32_t sB_u = (uint32_t)__cvta_generic_to_shared(sB);

    #pragma unroll
    for (int kc=0; kc<DD; kc+=64){
        __syncthreads();
        #pragma unroll
        for (int i=0;i<4;i++){
            int e = tid + i*256;
            int r = e >> 3, c8 = e & 7;
            size_t ga = (size_t)(bm*128 + r)*DD + kc + c8*8;
            size_t gb = (size_t)(bn*128 + r)*DD + kc + c8*8;
            *(uint4*)(sA + (r*SROW + c8*8)*2) = *(const uint4*)(g_xh + ga);
            *(uint4*)(sB + (r*SROW + c8*8)*2) = *(const uint4*)(g_xh + gb);
        }
        __syncthreads();

        #pragma unroll
        for (int ks=0; ks<4; ks++){
            uint32_t ah[2][4];
            #pragma unroll
            for (int t=0;t<2;t++){
                uint32_t ad = aoff + t*(16*SROW*2) + ks*32;
                LDSM4(ah[t][0],ah[t][1],ah[t][2],ah[t][3], sA_u + ad);
            }
            #pragma unroll
            for (int j=0;j<8;j++){
                uint32_t bh[2];
                uint32_t bd = boff + j*(8*SROW*2) + ks*32;
                LDSM2(bh[0],bh[1], sB_u + bd);
                #pragma unroll
                for (int t=0;t<2;t++)
                    MMA16816(c[t][j], ah[t], bh);
            }
        }
    }

    const int r0 = bm*128 + warpM + (lane >> 2);
    const int c0 = bn*128 + warpN + (lane & 3)*2;
    #pragma unroll
    for (int t=0;t<2;t++){
        #pragma unroll
        for (int j=0;j<8;j++){
            size_t base = (size_t)(r0 + t*16)*NPG + c0 + j*8;
            *(float2*)(g_sim + base)             = make_float2(c[t][j][0], c[t][j][1]);
            *(float2*)(g_sim + base + 8ull*NPG)  = make_float2(c[t][j][2], c[t][j][3]);
        }
    }
}

// ---------------- per-row top-32 candidates ----------------
__global__ __launch_bounds__(128) void k_topk(){
    __shared__ unsigned long long sk[128*16];
    __shared__ unsigned long long red[128];
    int row = blockIdx.x;
    int tid = threadIdx.x;
    const float* srow = g_sim + (size_t)row*NPG;

    unsigned long long t[16];
    #pragma unroll
    for (int r=0;r<16;r++) t[r]=0ull;

    for (int j=tid; j<NN; j+=128){
        float v = srow[j];
        unsigned u = __float_as_uint(v);
        u = (u & 0x80000000u) ? ~u : (u | 0x80000000u);
        unsigned long long key = ((unsigned long long)u << 32) | (unsigned)(~(unsigned)j);
        if (key > t[15]){
            t[15] = key;
            #pragma unroll
            for (int r=15;r>0;r--){
                if (t[r] > t[r-1]){ unsigned long long tmp=t[r-1]; t[r-1]=t[r]; t[r]=tmp; }
            }
        }
    }
    #pragma unroll
    for (int r=0;r<16;r++) sk[tid*16+r] = t[r];
    __syncthreads();

    for (int sel=0; sel<NCAND; sel++){
        unsigned long long m = sk[tid*16];
        #pragma unroll
        for (int r=1;r<16;r++) m = kmax64(m, sk[tid*16+r]);
        red[tid] = m;
        __syncthreads();
        for (int s=64;s>0;s>>=1){
            if (tid < s) red[tid] = kmax64(red[tid], red[tid+s]);
            __syncthreads();
        }
        unsigned long long best = red[0];
        if (tid == 0) g_cand[(size_t)row*NCAND + sel] = (int)(~(unsigned)(best & 0xffffffffull));
        #pragma unroll
        for (int r=0;r<16;r++) if (sk[tid*16+r] == best) sk[tid*16+r] = 0ull;
        __syncthreads();
    }
}

// ---------------- fp32 re-rank of 32 candidates -> top-16 ----------------
__global__ __launch_bounds__(256) void k_refine(){
    int w = threadIdx.x >> 5, lane = threadIdx.x & 31;
    int row = blockIdx.x*8 + w;
    if (row >= NN) return;
    float4 xr = *(const float4*)(g_xn + (size_t)row*DD + lane*4);
    int myidx = g_cand[(size_t)row*NCAND + lane];
    unsigned long long mykey = 0ull;
    #pragma unroll 4
    for (int c=0; c<NCAND; c++){
        int cand = __shfl_sync(0xffffffffu, myidx, c);
        float4 xc = *(const float4*)(g_xn + (size_t)cand*DD + lane*4);
        float p = xr.x*xc.x + xr.y*xc.y + xr.z*xc.z + xr.w*xc.w;
        #pragma unroll
        for (int o=16;o;o>>=1) p += __shfl_xor_sync(0xffffffffu, p, o);
        if (lane == c){
            unsigned u = __float_as_uint(p);
            u = (u & 0x80000000u) ? ~u : (u | 0x80000000u);
            mykey = ((unsigned long long)u << 32) | (unsigned)(~(unsigned)myidx);
        }
    }
    int rank = 0;
    #pragma unroll
    for (int peer=0; peer<32; peer++){
        unsigned long long pk = __shfl_sync(0xffffffffu, mykey, peer);
        rank += (pk > mykey) ? 1 : 0;
    }
    if (rank < 16) g_knn[(size_t)row*16 + rank] = myidx;
}

// ---------------- mult logits: mult[i][j][n] = <x[n,i], wKK[i,j]> + bKK ----
template<int K>
__global__ __launch_bounds__(256) void k_mult(const float* __restrict__ feats,
                                              const int* __restrict__ idx,
                                              int stride, int off0,
                                              const float* __restrict__ wKK,
                                              const float* __restrict__ bKK,
                                              size_t moff){
    __shared__ float4 xsT[32][65];
    __shared__ float  ws[16][128];
    __shared__ float  bsh[16];
    const int tid = threadIdx.x;
    const int i = blockIdx.y;
    const int jc = blockIdx.z;
    const int n0 = blockIdx.x*64;

    for (int e=tid; e<16*32; e+=256){
        int jl = e>>5, d4 = e&31;
        float4 v = *(const float4*)(wKK + ((size_t)(i*K + jc*16 + jl))*DD + d4*4);
        *(float4*)&ws[jl][d4*4] = v;
    }
    if (tid < 16) bsh[tid] = bKK[i*K + jc*16 + tid];

    for (int e=tid; e<64*32; e+=256){
        int nn = e>>5, d4 = e&31;
        int n = n0 + nn;
        int src;
        if (idx == nullptr) src = (n < NN) ? g_knn[(size_t)n*16 + i] : 0;
        else                src = (n < NN) ? idx[(size_t)n*stride + off0 + i] : 0;
        xsT[d4][nn] = *(const float4*)(feats + (size_t)src*DD + d4*4);
    }
    __syncthreads();

    const int n  = tid & 63;
    const int jg = tid >> 6;
    float acc[4] = {0.f,0.f,0.f,0.f};
    #pragma unroll
    for (int d4=0; d4<32; d4++){
        float4 xv = xsT[d4][n];
        #pragma unroll
        for (int jj=0; jj<4; jj++){
            float4 w = *(const float4*)&ws[jg*4+jj][d4*4];
            acc[jj] += xv.x*w.x + xv.y*w.y + xv.z*w.z + xv.w*w.w;
        }
    }
    float* mout = g_mult + moff;
    #pragma unroll
    for (int jj=0; jj<4; jj++){
        int jglob = jc*16 + jg*4 + jj;
        mout[((size_t)(i*K + jglob))*NP + n0 + n] = acc[jj] + bsh[jg*4+jj];
    }
}

// ---------------- coef[j][n] = sum_i wK1[i]*softmax_j(mult[i][:,n]) ---------
template<int K>
__global__ __launch_bounds__(256) void k_coef(size_t moff, size_t coff,
                                              const float* __restrict__ wK1){
    int n = blockIdx.x*256 + threadIdx.x;
    if (n >= NN) return;
    const float* mout = g_mult + moff;
    float cacc[K];
    #pragma unroll
    for (int j=0;j<K;j++) cacc[j]=0.f;
    #pragma unroll
    for (int i=0;i<K;i++){
        float v[K];
        float m = -1e30f;
        #pragma unroll
        for (int j=0;j<K;j++){
            v[j] = mout[((size_t)(i*K + j))*NP + n];
            m = fmaxf(m, v[j]);
        }
        float s = 0.f;
        #pragma unroll
        for (int j=0;j<K;j++){ v[j] = __expf(v[j]-m); s += v[j]; }
        float w = wK1[i] / s;
        #pragma unroll
        for (int j=0;j<K;j++) cacc[j] += w * v[j];
    }
    float* cout = g_coef + coff;
    #pragma unroll
    for (int j=0;j<K;j++) cout[(size_t)j*NP + n] = cacc[j];
}

// ---------------- hyper[n][t][:] = sum_j coef[j][n]*feats[idx(n,j)] + bK1 ---
template<int K>
__global__ __launch_bounds__(256) void k_hyper(const float* __restrict__ feats,
                                               const int* __restrict__ idx,
                                               int stride, int off0,
                                               size_t coff,
                                               const float* __restrict__ bK1,
                                               int t){
    int w = threadIdx.x >> 5, lane = threadIdx.x & 31;
    int n = blockIdx.x*8 + w;
    if (n >= NN) return;
    const float* coef = g_coef + coff;
    float4 acc = make_float4(0.f,0.f,0.f,0.f);
    #pragma unroll 4
    for (int j=0;j<K;j++){
        float c = __ldg(&coef[(size_t)j*NP + n]);
        int src = (idx == nullptr) ? g_knn[(size_t)n*16 + j]
                                   : idx[(size_t)n*stride + off0 + j];
        float4 f = *(const float4*)(feats + (size_t)src*DD + lane*4);
        acc.x += c*f.x; acc.y += c*f.y; acc.z += c*f.z; acc.w += c*f.w;
    }
    float b = bK1[0];
    acc.x += b; acc.y += b; acc.z += b; acc.w += b;
    *(float4*)(g_hyper + ((size_t)n*5 + t)*DD + lane*4) = acc;
}

// ---------------- EdgeConv attention + final FC ----------------
__global__ __launch_bounds__(128) void k_final(const float* __restrict__ ec_w1,
                                               const float* __restrict__ ec_b1,
                                               const float* __restrict__ ec_w2,
                                               const float* __restrict__ ec_b2,
                                               const float* __restrict__ fc_w,
                                               const float* __restrict__ fc_b,
                                               float* __restrict__ out){
    extern __shared__ float fsm[];
    float* fcw  = fsm;
    float* w1s  = fsm + 16384;
    float* xs   = fsm + 16384 + 4096;
    float* aggs = xs + 4*640;
    int tid = threadIdx.x;
    for (int e=tid; e<16384/4; e+=128)
        *(float4*)&fcw[e*4] = *(const float4*)&fc_w[e*4];
    for (int e=tid; e<4096/4; e+=128)
        *(float4*)&w1s[e*4] = *(const float4*)&ec_w1[e*4];
    __syncthreads();

    int w = tid >> 5, lane = tid & 31;
    int n = blockIdx.x*4 + w;

    float4 xr[5];
    #pragma unroll
    for (int t=0;t<5;t++){
        xr[t] = *(const float4*)(g_hyper + ((size_t)n*5 + t)*DD + lane*4);
        *(float4*)&xs[w*640 + t*128 + lane*4] = xr[t];
    }
    __syncwarp();

    float w2v = ec_w2[lane];
    float b1v = ec_b1[lane];
    float sc[5];
    #pragma unroll
    for (int t=0;t<5;t++){
        float h = b1v;
        #pragma unroll 4
        for (int d=0; d<DD; d++)
            h += xs[w*640 + t*128 + d] * w1s[d*32 + lane];
        h = fmaxf(h, 0.f);
        float p = h * w2v;
        #pragma unroll
        for (int o=16;o;o>>=1) p += __shfl_xor_sync(0xffffffffu, p, o);
        sc[t] = p;
    }
    float b2 = ec_b2[0];
    float m = -1e30f;
    #pragma unroll
    for (int t=0;t<5;t++){ sc[t] += b2; m = fmaxf(m, sc[t]); }
    float s = 0.f;
    #pragma unroll
    for (int t=0;t<5;t++){ sc[t] = __expf(sc[t]-m); s += sc[t]; }
    float inv = 1.f/s;
    #pragma unroll
    for (int t=0;t<5;t++) sc[t] *= inv;

    float4 a = make_float4(0.f,0.f,0.f,0.f);
    #pragma unroll
    for (int t=0;t<5;t++){
        a.x += sc[t]*xr[t].x; a.y += sc[t]*xr[t].y;
        a.z += sc[t]*xr[t].z; a.w += sc[t]*xr[t].w;
    }
    *(float4*)&aggs[w*128 + lane*4] = a;
    __syncwarp();

    float4 o = *(const float4*)&fc_b[lane*4];
    #pragma unroll 4
    for (int d=0; d<DD; d++){
        float av = aggs[w*128 + d];
        float4 fw = *(const float4*)&fcw[d*128 + lane*4];
        o.x += av*fw.x; o.y += av*fw.y; o.z += av*fw.z; o.w += av*fw.w;
    }
    o.x = fmaxf(o.x,0.f); o.y = fmaxf(o.y,0.f);
    o.z = fmaxf(o.z,0.f); o.w = fmaxf(o.w,0.f);
    *(float4*)(out + (size_t)n*DD + lane*4) = o;
}

// ---------------- launch ----------------
extern "C" void kernel_launch(void* const* d_in, const int* in_sizes, int n_in,
                              void* d_out, int out_size){
    const float* feats  = (const float*)d_in[1];
    const int*   cidx   = (const int*)d_in[2];
    const int*   sidx   = (const int*)d_in[3];
    const float* wKK_c  = (const float*)d_in[5];
    const float* bKK_c  = (const float*)d_in[6];
    const float* wK1_c  = (const float*)d_in[7];
    const float* bK1_c  = (const float*)d_in[8];
    const float* wKK_n  = (const float*)d_in[9];
    const float* bKK_n  = (const float*)d_in[10];
    const float* wK1_n  = (const float*)d_in[11];
    const float* bK1_n  = (const float*)d_in[12];
    const float* wKK_s  = (const float*)d_in[13];
    const float* bKK_s  = (const float*)d_in[14];
    const float* wK1_s  = (const float*)d_in[15];
    const float* bK1_s  = (const float*)d_in[16];
    const float* ec_w1  = (const float*)d_in[17];
    const float* ec_b1  = (const float*)d_in[18];
    const float* ec_w2  = (const float*)d_in[19];
    const float* ec_b2  = (const float*)d_in[20];
    const float* fc_w   = (const float*)d_in[21];
    const float* fc_b   = (const float*)d_in[22];
    float* out = (float*)d_out;

    cudaFuncSetAttribute(k_simT, cudaFuncAttributeMaxDynamicSharedMemorySize, SIM_SMEM);
    cudaFuncSetAttribute(k_final, cudaFuncAttributeMaxDynamicSharedMemorySize, 94208);

    k_norm<<<NPG/8, 256>>>(feats);
    k_simT<<<dim3(NPG/128, NPG/128), 256, SIM_SMEM>>>();
    k_topk<<<NN, 128>>>();
    k_refine<<<(NN+7)/8, 256>>>();

    const size_t M16 = (size_t)256*NP;
    for (int c=0;c<3;c++)
        k_mult<16><<<dim3(NP/64,16,1),256>>>(feats, cidx, 48, c*16, wKK_c, bKK_c, (size_t)c*M16);
    k_mult<16><<<dim3(NP/64,16,1),256>>>(feats, nullptr, 16, 0, wKK_n, bKK_n, 3*M16);
    k_mult<32><<<dim3(NP/64,32,2),256>>>(feats, sidx, 32, 0, wKK_s, bKK_s, 4*M16);

    int cb = (NN + 255)/256;
    for (int c=0;c<3;c++)
        k_coef<16><<<cb,256>>>((size_t)c*M16, (size_t)c*16*NP, wK1_c);
    k_coef<16><<<cb,256>>>(3*M16, (size_t)48*NP, wK1_n);
    k_coef<32><<<cb,256>>>(4*M16, (size_t)64*NP, wK1_s);

    for (int c=0;c<3;c++)
        k_hyper<16><<<NN/8,256>>>(feats, cidx, 48, c*16, (size_t)c*16*NP, bK1_c, c);
    k_hyper<16><<<NN/8,256>>>(feats, nullptr, 16, 0, (size_t)48*NP, bK1_n, 3);
    k_hyper<32><<<NN/8,256>>>(feats, sidx, 32, 0, (size_t)64*NP, bK1_s, 4);

    k_final<<<NN/4, 128, 94208>>>(ec_w1, ec_b1, ec_w2, ec_b2, fc_w, fc_b, out);
}

// round 9
// speedup vs baseline: 2.6741x; 2.6741x over previous
#include <cuda_runtime.h>
#include <cuda_bf16.h>
#include <cstdint>
#include <cstddef>

#define NN   10000
#define NP   10048          // padding for the elementwise/mult kernels (157*64)
#define NPG  10112          // padding for the GEMM/topk (79*128)
#define DD   128
#define NCAND 32

// ---------------- device scratch ----------------
__device__ float g_xn[(size_t)NPG*DD];              // normalized fp32
__device__ __nv_bfloat16 g_xh[(size_t)NPG*DD];      // bf16 of normalized
__device__ float g_sim[(size_t)NPG*NPG];
__device__ int   g_cand[(size_t)NN*NCAND];
__device__ int   g_knn[(size_t)NN*16];
__device__ float g_mult[(size_t)2048*NP];           // [i][j][NP] per branch
__device__ float g_coef[(size_t)96*NP];             // [j][NP] per branch
__device__ float g_hyper[(size_t)NN*5*DD];

__device__ __forceinline__ unsigned long long kmax64(unsigned long long a, unsigned long long b){
    return a > b ? a : b;
}

// ---------------- normalize rows -> fp32 + bf16 ----------------
__global__ __launch_bounds__(256) void k_norm(const float* __restrict__ feats){
    int w = threadIdx.x >> 5, lane = threadIdx.x & 31;
    int row = blockIdx.x*8 + w;
    if (row >= NPG) return;
    float4 v = make_float4(0.f,0.f,0.f,0.f);
    if (row < NN){
        v = *(const float4*)(feats + (size_t)row*DD + lane*4);
        float ss = v.x*v.x + v.y*v.y + v.z*v.z + v.w*v.w;
        #pragma unroll
        for (int o=16;o;o>>=1) ss += __shfl_xor_sync(0xffffffffu, ss, o);
        float inv = 1.0f / fmaxf(sqrtf(ss), 1e-12f);
        v.x*=inv; v.y*=inv; v.z*=inv; v.w*=inv;
    }
    *(float4*)(g_xn + (size_t)row*DD + lane*4) = v;
    __nv_bfloat16 hi[4] = { __float2bfloat16_rn(v.x), __float2bfloat16_rn(v.y),
                            __float2bfloat16_rn(v.z), __float2bfloat16_rn(v.w) };
    *(uint2*)(g_xh + (size_t)row*DD + lane*4) = *(uint2*)hi;
}

// ---------------- approx sim = xh @ xh^T (single-pass bf16 HMMA) ----------
#define LDSM4(r0,r1,r2,r3,addr) \
    asm volatile("ldmatrix.sync.aligned.m8n8.x4.shared.b16 {%0,%1,%2,%3},[%4];" \
        : "=r"(r0),"=r"(r1),"=r"(r2),"=r"(r3) : "r"(addr))
#define LDSM2(r0,r1,addr) \
    asm volatile("ldmatrix.sync.aligned.m8n8.x2.shared.b16 {%0,%1},[%2];" \
        : "=r"(r0),"=r"(r1) : "r"(addr))
#define MMA16816(c,a,b) \
    asm volatile("mma.sync.aligned.m16n8k16.row.col.f32.bf16.bf16.f32 " \
        "{%0,%1,%2,%3},{%4,%5,%6,%7},{%8,%9},{%0,%1,%2,%3};" \
        : "+f"(c[0]),"+f"(c[1]),"+f"(c[2]),"+f"(c[3]) \
        : "r"(a[0]),"r"(a[1]),"r"(a[2]),"r"(a[3]),"r"(b[0]),"r"(b[1]))

#define SROW2 136        // smem row stride in bf16 (272B) — conflict-free ldmatrix
#define SIM_SMEM (2*128*SROW2*2)   // 69632 bytes

__global__ __launch_bounds__(256) void k_simT(){
    extern __shared__ __align__(16) char smem[];
    char* sA = smem;
    char* sB = smem + 128*SROW2*2;

    const int tid  = threadIdx.x;
    const int wid  = tid >> 5;
    const int lane = tid & 31;
    const int bm = blockIdx.y, bn = blockIdx.x;
    const int warpM = (wid & 3) * 32;
    const int warpN = (wid >> 2) * 64;

    float c[2][8][4];
    #pragma unroll
    for (int t=0;t<2;t++)
        #pragma unroll
        for (int j=0;j<8;j++)
            #pragma unroll
            for (int q=0;q<4;q++) c[t][j][q] = 0.f;

    // load full 128x128 bf16 tiles once (8 uint4 per thread per matrix)
    #pragma unroll
    for (int i=0;i<8;i++){
        int e = tid + i*256;
        int r = e >> 4, c8 = e & 15;
        size_t ga = (size_t)(bm*128 + r)*DD + c8*8;
        size_t gb = (size_t)(bn*128 + r)*DD + c8*8;
        *(uint4*)(sA + (r*SROW2 + c8*8)*2) = *(const uint4*)(g_xh + ga);
        *(uint4*)(sB + (r*SROW2 + c8*8)*2) = *(const uint4*)(g_xh + gb);
    }
    __syncthreads();

    uint32_t aoff = (uint32_t)((warpM + (lane & 15))*SROW2*2 + (lane >> 4)*16);
    uint32_t boff = (uint32_t)((warpN + (lane & 7))*SROW2*2 + ((lane >> 3) & 1)*16);
    uint32_t sA_u = (uint32_t)__cvta_generic_to_shared(sA);
    uint32_t sB_u = (uint32_t)__cvta_generic_to_shared(sB);

    #pragma unroll
    for (int ks=0; ks<8; ks++){
        uint32_t ah[2][4];
        #pragma unroll
        for (int t=0;t<2;t++){
            uint32_t ad = aoff + t*(16*SROW2*2) + ks*32;
            LDSM4(ah[t][0],ah[t][1],ah[t][2],ah[t][3], sA_u + ad);
        }
        #pragma unroll
        for (int j=0;j<8;j++){
            uint32_t bh[2];
            uint32_t bd = boff + j*(8*SROW2*2) + ks*32;
            LDSM2(bh[0],bh[1], sB_u + bd);
            #pragma unroll
            for (int t=0;t<2;t++)
                MMA16816(c[t][j], ah[t], bh);
        }
    }

    const int r0 = bm*128 + warpM + (lane >> 2);
    const int c0 = bn*128 + warpN + (lane & 3)*2;
    #pragma unroll
    for (int t=0;t<2;t++){
        #pragma unroll
        for (int j=0;j<8;j++){
            size_t base = (size_t)(r0 + t*16)*NPG + c0 + j*8;
            *(float2*)(g_sim + base)             = make_float2(c[t][j][0], c[t][j][1]);
            *(float2*)(g_sim + base + 8ull*NPG)  = make_float2(c[t][j][2], c[t][j][3]);
        }
    }
}

// ---------------- per-row top-32 candidates (register-max selection) -------
__global__ __launch_bounds__(128) void k_topk(){
    __shared__ unsigned long long sk[16][128];
    __shared__ unsigned long long wmax[4];
    int row = blockIdx.x;
    int tid = threadIdx.x;
    const float* srow = g_sim + (size_t)row*NPG;

    unsigned long long t[16];
    #pragma unroll
    for (int r=0;r<16;r++) t[r]=0ull;

    for (int j=tid; j<NN; j+=128){
        float v = srow[j];
        unsigned u = __float_as_uint(v);
        u = (u & 0x80000000u) ? ~u : (u | 0x80000000u);
        unsigned long long key = ((unsigned long long)u << 32) | (unsigned)(~(unsigned)j);
        if (key > t[15]){
            t[15] = key;
            #pragma unroll
            for (int r=15;r>0;r--){
                if (t[r] > t[r-1]){ unsigned long long tmp=t[r-1]; t[r-1]=t[r]; t[r]=tmp; }
            }
        }
    }
    #pragma unroll
    for (int r=0;r<16;r++) sk[r][tid] = t[r];
    unsigned long long lmax = t[0];          // t is sorted desc
    __syncthreads();

    for (int sel=0; sel<NCAND; sel++){
        unsigned long long m = lmax;
        #pragma unroll
        for (int o=16;o;o>>=1) m = kmax64(m, __shfl_xor_sync(0xffffffffu, m, o));
        if ((tid & 31) == 0) wmax[tid >> 5] = m;
        __syncthreads();
        unsigned long long best = kmax64(kmax64(wmax[0],wmax[1]), kmax64(wmax[2],wmax[3]));
        if (lmax == best){
            #pragma unroll
            for (int r=0;r<16;r++){
                if (sk[r][tid] == best){ sk[r][tid] = 0ull; break; }
            }
            unsigned long long nm = 0ull;
            #pragma unroll
            for (int r=0;r<16;r++) nm = kmax64(nm, sk[r][tid]);
            lmax = nm;
        }
        if (tid == 0) g_cand[(size_t)row*NCAND + sel] = (int)(~(unsigned)(best & 0xffffffffull));
        __syncthreads();
    }
}

// ---------------- fp32 re-rank of 32 candidates -> top-16 ----------------
__global__ __launch_bounds__(256) void k_refine(){
    int w = threadIdx.x >> 5, lane = threadIdx.x & 31;
    int row = blockIdx.x*8 + w;
    if (row >= NN) return;
    float4 xr = *(const float4*)(g_xn + (size_t)row*DD + lane*4);
    int myidx = g_cand[(size_t)row*NCAND + lane];
    unsigned long long mykey = 0ull;
    #pragma unroll 4
    for (int c=0; c<NCAND; c++){
        int cand = __shfl_sync(0xffffffffu, myidx, c);
        float4 xc = *(const float4*)(g_xn + (size_t)cand*DD + lane*4);
        float p = xr.x*xc.x + xr.y*xc.y + xr.z*xc.z + xr.w*xc.w;
        #pragma unroll
        for (int o=16;o;o>>=1) p += __shfl_xor_sync(0xffffffffu, p, o);
        if (lane == c){
            unsigned u = __float_as_uint(p);
            u = (u & 0x80000000u) ? ~u : (u | 0x80000000u);
            mykey = ((unsigned long long)u << 32) | (unsigned)(~(unsigned)myidx);
        }
    }
    int rank = 0;
    #pragma unroll
    for (int peer=0; peer<32; peer++){
        unsigned long long pk = __shfl_sync(0xffffffffu, mykey, peer);
        rank += (pk > mykey) ? 1 : 0;
    }
    if (rank < 16) g_knn[(size_t)row*16 + rank] = myidx;
}

// ---------------- mult logits: mult[i][j][n] = <x[n,i], wKK[i,j]> + bKK ----
template<int K>
__global__ __launch_bounds__(256) void k_mult(const float* __restrict__ feats,
                                              const int* __restrict__ idx,
                                              int stride, int off0,
                                              const float* __restrict__ wKK,
                                              const float* __restrict__ bKK,
                                              size_t moff){
    __shared__ float4 xsT[32][65];
    __shared__ float  ws[16][128];
    __shared__ float  bsh[16];
    const int tid = threadIdx.x;
    const int i = blockIdx.y;
    const int jc = blockIdx.z;
    const int n0 = blockIdx.x*64;

    for (int e=tid; e<16*32; e+=256){
        int jl = e>>5, d4 = e&31;
        float4 v = *(const float4*)(wKK + ((size_t)(i*K + jc*16 + jl))*DD + d4*4);
        *(float4*)&ws[jl][d4*4] = v;
    }
    if (tid < 16) bsh[tid] = bKK[i*K + jc*16 + tid];

    for (int e=tid; e<64*32; e+=256){
        int nn = e>>5, d4 = e&31;
        int n = n0 + nn;
        int src;
        if (idx == nullptr) src = (n < NN) ? g_knn[(size_t)n*16 + i] : 0;
        else                src = (n < NN) ? idx[(size_t)n*stride + off0 + i] : 0;
        xsT[d4][nn] = *(const float4*)(feats + (size_t)src*DD + d4*4);
    }
    __syncthreads();

    const int n  = tid & 63;
    const int jg = tid >> 6;
    float acc[4] = {0.f,0.f,0.f,0.f};
    #pragma unroll
    for (int d4=0; d4<32; d4++){
        float4 xv = xsT[d4][n];
        #pragma unroll
        for (int jj=0; jj<4; jj++){
            float4 w = *(const float4*)&ws[jg*4+jj][d4*4];
            acc[jj] += xv.x*w.x + xv.y*w.y + xv.z*w.z + xv.w*w.w;
        }
    }
    float* mout = g_mult + moff;
    #pragma unroll
    for (int jj=0; jj<4; jj++){
        int jglob = jc*16 + jg*4 + jj;
        mout[((size_t)(i*K + jglob))*NP + n0 + n] = acc[jj] + bsh[jg*4+jj];
    }
}

// ---------------- coef[j][n] = sum_i wK1[i]*softmax_j(mult[i][:,n]) ---------
template<int K>
__global__ __launch_bounds__(256) void k_coef(size_t moff, size_t coff,
                                              const float* __restrict__ wK1){
    int n = blockIdx.x*256 + threadIdx.x;
    if (n >= NN) return;
    const float* mout = g_mult + moff;
    float cacc[K];
    #pragma unroll
    for (int j=0;j<K;j++) cacc[j]=0.f;
    #pragma unroll
    for (int i=0;i<K;i++){
        float v[K];
        float m = -1e30f;
        #pragma unroll
        for (int j=0;j<K;j++){
            v[j] = mout[((size_t)(i*K + j))*NP + n];
            m = fmaxf(m, v[j]);
        }
        float s = 0.f;
        #pragma unroll
        for (int j=0;j<K;j++){ v[j] = __expf(v[j]-m); s += v[j]; }
        float w = wK1[i] / s;
        #pragma unroll
        for (int j=0;j<K;j++) cacc[j] += w * v[j];
    }
    float* cout = g_coef + coff;
    #pragma unroll
    for (int j=0;j<K;j++) cout[(size_t)j*NP + n] = cacc[j];
}

// ---------------- hyper[n][t][:] = sum_j coef[j][n]*feats[idx(n,j)] + bK1 ---
template<int K>
__global__ __launch_bounds__(256) void k_hyper(const float* __restrict__ feats,
                                               const int* __restrict__ idx,
                                               int stride, int off0,
                                               size_t coff,
                                               const float* __restrict__ bK1,
                                               int t){
    int w = threadIdx.x >> 5, lane = threadIdx.x & 31;
    int n = blockIdx.x*8 + w;
    if (n >= NN) return;
    const float* coef = g_coef + coff;
    float4 acc = make_float4(0.f,0.f,0.f,0.f);
    #pragma unroll 4
    for (int j=0;j<K;j++){
        float c = __ldg(&coef[(size_t)j*NP + n]);
        int src = (idx == nullptr) ? g_knn[(size_t)n*16 + j]
                                   : idx[(size_t)n*stride + off0 + j];
        float4 f = *(const float4*)(feats + (size_t)src*DD + lane*4);
        acc.x += c*f.x; acc.y += c*f.y; acc.z += c*f.z; acc.w += c*f.w;
    }
    float b = bK1[0];
    acc.x += b; acc.y += b; acc.z += b; acc.w += b;
    *(float4*)(g_hyper + ((size_t)n*5 + t)*DD + lane*4) = acc;
}

// ---------------- EdgeConv attention + final FC ----------------
__global__ __launch_bounds__(128) void k_final(const float* __restrict__ ec_w1,
                                               const float* __restrict__ ec_b1,
                                               const float* __restrict__ ec_w2,
                                               const float* __restrict__ ec_b2,
                                               const float* __restrict__ fc_w,
                                               const float* __restrict__ fc_b,
                                               float* __restrict__ out){
    extern __shared__ float fsm[];
    float* fcw  = fsm;
    float* w1s  = fsm + 16384;
    float* xs   = fsm + 16384 + 4096;
    float* aggs = xs + 4*640;
    int tid = threadIdx.x;
    for (int e=tid; e<16384/4; e+=128)
        *(float4*)&fcw[e*4] = *(const float4*)&fc_w[e*4];
    for (int e=tid; e<4096/4; e+=128)
        *(float4*)&w1s[e*4] = *(const float4*)&ec_w1[e*4];
    __syncthreads();

    int w = tid >> 5, lane = tid & 31;
    int n = blockIdx.x*4 + w;

    float4 xr[5];
    #pragma unroll
    for (int t=0;t<5;t++){
        xr[t] = *(const float4*)(g_hyper + ((size_t)n*5 + t)*DD + lane*4);
        *(float4*)&xs[w*640 + t*128 + lane*4] = xr[t];
    }
    __syncwarp();

    float w2v = ec_w2[lane];
    float b1v = ec_b1[lane];
    float sc[5];
    #pragma unroll
    for (int t=0;t<5;t++){
        float h = b1v;
        #pragma unroll 4
        for (int d=0; d<DD; d++)
            h += xs[w*640 + t*128 + d] * w1s[d*32 + lane];
        h = fmaxf(h, 0.f);
        float p = h * w2v;
        #pragma unroll
        for (int o=16;o;o>>=1) p += __shfl_xor_sync(0xffffffffu, p, o);
        sc[t] = p;
    }
    float b2 = ec_b2[0];
    float m = -1e30f;
    #pragma unroll
    for (int t=0;t<5;t++){ sc[t] += b2; m = fmaxf(m, sc[t]); }
    float s = 0.f;
    #pragma unroll
    for (int t=0;t<5;t++){ sc[t] = __expf(sc[t]-m); s += sc[t]; }
    float inv = 1.f/s;
    #pragma unroll
    for (int t=0;t<5;t++) sc[t] *= inv;

    float4 a = make_float4(0.f,0.f,0.f,0.f);
    #pragma unroll
    for (int t=0;t<5;t++){
        a.x += sc[t]*xr[t].x; a.y += sc[t]*xr[t].y;
        a.z += sc[t]*xr[t].z; a.w += sc[t]*xr[t].w;
    }
    *(float4*)&aggs[w*128 + lane*4] = a;
    __syncwarp();

    float4 o = *(const float4*)&fc_b[lane*4];
    #pragma unroll 4
    for (int d=0; d<DD; d++){
        float av = aggs[w*128 + d];
        float4 fw = *(const float4*)&fcw[d*128 + lane*4];
        o.x += av*fw.x; o.y += av*fw.y; o.z += av*fw.z; o.w += av*fw.w;
    }
    o.x = fmaxf(o.x,0.f); o.y = fmaxf(o.y,0.f);
    o.z = fmaxf(o.z,0.f); o.w = fmaxf(o.w,0.f);
    *(float4*)(out + (size_t)n*DD + lane*4) = o;
}

// ---------------- launch ----------------
extern "C" void kernel_launch(void* const* d_in, const int* in_sizes, int n_in,
                              void* d_out, int out_size){
    const float* feats  = (const float*)d_in[1];
    const int*   cidx   = (const int*)d_in[2];
    const int*   sidx   = (const int*)d_in[3];
    const float* wKK_c  = (const float*)d_in[5];
    const float* bKK_c  = (const float*)d_in[6];
    const float* wK1_c  = (const float*)d_in[7];
    const float* bK1_c  = (const float*)d_in[8];
    const float* wKK_n  = (const float*)d_in[9];
    const float* bKK_n  = (const float*)d_in[10];
    const float* wK1_n  = (const float*)d_in[11];
    const float* bK1_n  = (const float*)d_in[12];
    const float* wKK_s  = (const float*)d_in[13];
    const float* bKK_s  = (const float*)d_in[14];
    const float* wK1_s  = (const float*)d_in[15];
    const float* bK1_s  = (const float*)d_in[16];
    const float* ec_w1  = (const float*)d_in[17];
    const float* ec_b1  = (const float*)d_in[18];
    const float* ec_w2  = (const float*)d_in[19];
    const float* ec_b2  = (const float*)d_in[20];
    const float* fc_w   = (const float*)d_in[21];
    const float* fc_b   = (const float*)d_in[22];
    float* out = (float*)d_out;

    cudaFuncSetAttribute(k_simT, cudaFuncAttributeMaxDynamicSharedMemorySize, SIM_SMEM);
    cudaFuncSetAttribute(k_final, cudaFuncAttributeMaxDynamicSharedMemorySize, 94208);

    k_norm<<<NPG/8, 256>>>(feats);
    k_simT<<<dim3(NPG/128, NPG/128), 256, SIM_SMEM>>>();
    k_topk<<<NN, 128>>>();
    k_refine<<<(NN+7)/8, 256>>>();

    const size_t M16 = (size_t)256*NP;
    for (int c=0;c<3;c++)
        k_mult<16><<<dim3(NP/64,16,1),256>>>(feats, cidx, 48, c*16, wKK_c, bKK_c, (size_t)c*M16);
    k_mult<16><<<dim3(NP/64,16,1),256>>>(feats, nullptr, 16, 0, wKK_n, bKK_n, 3*M16);
    k_mult<32><<<dim3(NP/64,32,2),256>>>(feats, sidx, 32, 0, wKK_s, bKK_s, 4*M16);

    int cb = (NN + 255)/256;
    for (int c=0;c<3;c++)
        k_coef<16><<<cb,256>>>((size_t)c*M16, (size_t)c*16*NP, wK1_c);
    k_coef<16><<<cb,256>>>(3*M16, (size_t)48*NP, wK1_n);
    k_coef<32><<<cb,256>>>(4*M16, (size_t)64*NP, wK1_s);

    for (int c=0;c<3;c++)
        k_hyper<16><<<NN/8,256>>>(feats, cidx, 48, c*16, (size_t)c*16*NP, bK1_c, c);
    k_hyper<16><<<NN/8,256>>>(feats, nullptr, 16, 0, (size_t)48*NP, bK1_n, 3);
    k_hyper<32><<<NN/8,256>>>(feats, sidx, 32, 0, (size_t)64*NP, bK1_s, 4);

    k_final<<<NN/4, 128, 94208>>>(ec_w1, ec_b1, ec_w2, ec_b2, fc_w, fc_b, out);
}

// round 10
// speedup vs baseline: 4.7390x; 1.7721x over previous
#include <cuda_runtime.h>
#include <cuda_bf16.h>
#include <cstdint>
#include <cstddef>

#define NN   10000
#define NP   10048          // padding for the elementwise/mult kernels (157*64)
#define NPG  10112          // padding for the GEMM/topk (79*128)
#define DD   128
#define NCAND 32

// ---------------- device scratch ----------------
__device__ float g_xn[(size_t)NPG*DD];              // normalized fp32
__device__ __nv_bfloat16 g_xh[(size_t)NPG*DD];      // bf16 of normalized
__device__ __nv_bfloat16 g_simh[(size_t)NPG*NPG];   // bf16 sim (202 MB)
__device__ int   g_cand[(size_t)NN*NCAND];
__device__ int   g_knn[(size_t)NN*16];
__device__ float g_mult[(size_t)2048*NP];           // [i][j][NP] per branch
__device__ float g_coef[(size_t)96*NP];             // [j][NP] per branch
__device__ float g_hyper[(size_t)NN*5*DD];

__device__ __forceinline__ uint32_t kmax32(uint32_t a, uint32_t b){ return a>b?a:b; }

// ---------------- normalize rows -> fp32 + bf16 ----------------
__global__ __launch_bounds__(256) void k_norm(const float* __restrict__ feats){
    int w = threadIdx.x >> 5, lane = threadIdx.x & 31;
    int row = blockIdx.x*8 + w;
    if (row >= NPG) return;
    float4 v = make_float4(0.f,0.f,0.f,0.f);
    if (row < NN){
        v = *(const float4*)(feats + (size_t)row*DD + lane*4);
        float ss = v.x*v.x + v.y*v.y + v.z*v.z + v.w*v.w;
        #pragma unroll
        for (int o=16;o;o>>=1) ss += __shfl_xor_sync(0xffffffffu, ss, o);
        float inv = 1.0f / fmaxf(sqrtf(ss), 1e-12f);
        v.x*=inv; v.y*=inv; v.z*=inv; v.w*=inv;
    }
    *(float4*)(g_xn + (size_t)row*DD + lane*4) = v;
    __nv_bfloat16 hi[4] = { __float2bfloat16_rn(v.x), __float2bfloat16_rn(v.y),
                            __float2bfloat16_rn(v.z), __float2bfloat16_rn(v.w) };
    *(uint2*)(g_xh + (size_t)row*DD + lane*4) = *(uint2*)hi;
}

// ---------------- approx sim = xh @ xh^T (single-pass bf16 HMMA) ----------
#define LDSM4(r0,r1,r2,r3,addr) \
    asm volatile("ldmatrix.sync.aligned.m8n8.x4.shared.b16 {%0,%1,%2,%3},[%4];" \
        : "=r"(r0),"=r"(r1),"=r"(r2),"=r"(r3) : "r"(addr))
#define LDSM2(r0,r1,addr) \
    asm volatile("ldmatrix.sync.aligned.m8n8.x2.shared.b16 {%0,%1},[%2];" \
        : "=r"(r0),"=r"(r1) : "r"(addr))
#define MMA16816(c,a,b) \
    asm volatile("mma.sync.aligned.m16n8k16.row.col.f32.bf16.bf16.f32 " \
        "{%0,%1,%2,%3},{%4,%5,%6,%7},{%8,%9},{%0,%1,%2,%3};" \
        : "+f"(c[0]),"+f"(c[1]),"+f"(c[2]),"+f"(c[3]) \
        : "r"(a[0]),"r"(a[1]),"r"(a[2]),"r"(a[3]),"r"(b[0]),"r"(b[1]))

#define SROW2 136        // smem row stride in bf16 (272B) — conflict-free ldmatrix
#define SIM_SMEM (2*128*SROW2*2)   // 69632 bytes

__global__ __launch_bounds__(256) void k_simT(){
    extern __shared__ __align__(16) char smem[];
    char* sA = smem;
    char* sB = smem + 128*SROW2*2;

    const int tid  = threadIdx.x;
    const int wid  = tid >> 5;
    const int lane = tid & 31;
    const int bm = blockIdx.y, bn = blockIdx.x;
    const int warpM = (wid & 3) * 32;
    const int warpN = (wid >> 2) * 64;

    float c[2][8][4];
    #pragma unroll
    for (int t=0;t<2;t++)
        #pragma unroll
        for (int j=0;j<8;j++)
            #pragma unroll
            for (int q=0;q<4;q++) c[t][j][q] = 0.f;

    #pragma unroll
    for (int i=0;i<8;i++){
        int e = tid + i*256;
        int r = e >> 4, c8 = e & 15;
        size_t ga = (size_t)(bm*128 + r)*DD + c8*8;
        size_t gb = (size_t)(bn*128 + r)*DD + c8*8;
        *(uint4*)(sA + (r*SROW2 + c8*8)*2) = *(const uint4*)(g_xh + ga);
        *(uint4*)(sB + (r*SROW2 + c8*8)*2) = *(const uint4*)(g_xh + gb);
    }
    __syncthreads();

    uint32_t aoff = (uint32_t)((warpM + (lane & 15))*SROW2*2 + (lane >> 4)*16);
    uint32_t boff = (uint32_t)((warpN + (lane & 7))*SROW2*2 + ((lane >> 3) & 1)*16);
    uint32_t sA_u = (uint32_t)__cvta_generic_to_shared(sA);
    uint32_t sB_u = (uint32_t)__cvta_generic_to_shared(sB);

    #pragma unroll
    for (int ks=0; ks<8; ks++){
        uint32_t ah[2][4];
        #pragma unroll
        for (int t=0;t<2;t++){
            uint32_t ad = aoff + t*(16*SROW2*2) + ks*32;
            LDSM4(ah[t][0],ah[t][1],ah[t][2],ah[t][3], sA_u + ad);
        }
        #pragma unroll
        for (int j=0;j<8;j++){
            uint32_t bh[2];
            uint32_t bd = boff + j*(8*SROW2*2) + ks*32;
            LDSM2(bh[0],bh[1], sB_u + bd);
            #pragma unroll
            for (int t=0;t<2;t++)
                MMA16816(c[t][j], ah[t], bh);
        }
    }

    const int r0 = bm*128 + warpM + (lane >> 2);
    const int c0 = bn*128 + warpN + (lane & 3)*2;
    #pragma unroll
    for (int t=0;t<2;t++){
        #pragma unroll
        for (int j=0;j<8;j++){
            size_t base = (size_t)(r0 + t*16)*NPG + c0 + j*8;
            *(__nv_bfloat162*)(g_simh + base) =
                __float22bfloat162_rn(make_float2(c[t][j][0], c[t][j][1]));
            *(__nv_bfloat162*)(g_simh + base + 8ull*NPG) =
                __float22bfloat162_rn(make_float2(c[t][j][2], c[t][j][3]));
        }
    }
}

// ---------------- per-row top-32 candidates (bf16 keys, u32 selection) -----
__device__ __forceinline__ uint32_t bf16key(uint32_t u16, int j){
    uint32_t m = (u16 & 0x8000u) ? ((~u16) & 0xFFFFu) : (u16 | 0x8000u);
    return (m << 14) | (uint32_t)(16383 - j);
}

__global__ __launch_bounds__(128) void k_topk(){
    __shared__ uint32_t sk[16][128];
    __shared__ uint32_t wmax[4];
    int row = blockIdx.x;
    int tid = threadIdx.x;
    const uint4* srow4 = (const uint4*)(g_simh + (size_t)row*NPG);

    uint32_t t[16];
    #pragma unroll
    for (int r=0;r<16;r++) t[r]=0u;

    #pragma unroll 1
    for (int it=0; it<10; it++){
        int v4 = it*128 + tid;
        if (v4 >= 1250) break;          // 1250*8 == 10000 exactly
        uint4 q = srow4[v4];
        int jb = v4*8;
        uint32_t ws[4] = {q.x, q.y, q.z, q.w};
        #pragma unroll
        for (int wv=0; wv<4; wv++){
            uint32_t klo = bf16key(ws[wv] & 0xFFFFu, jb + wv*2);
            uint32_t khi = bf16key(ws[wv] >> 16,     jb + wv*2 + 1);
            if (klo > t[15]){
                t[15] = klo;
                #pragma unroll
                for (int r=15;r>0;r--)
                    if (t[r] > t[r-1]){ uint32_t tmp=t[r-1]; t[r-1]=t[r]; t[r]=tmp; }
            }
            if (khi > t[15]){
                t[15] = khi;
                #pragma unroll
                for (int r=15;r>0;r--)
                    if (t[r] > t[r-1]){ uint32_t tmp=t[r-1]; t[r-1]=t[r]; t[r]=tmp; }
            }
        }
    }
    #pragma unroll
    for (int r=0;r<16;r++) sk[r][tid] = t[r];
    uint32_t lmax = t[0];               // t sorted desc
    __syncthreads();

    for (int sel=0; sel<NCAND; sel++){
        uint32_t m = lmax;
        #pragma unroll
        for (int o=16;o;o>>=1) m = kmax32(m, __shfl_xor_sync(0xffffffffu, m, o));
        if ((tid & 31) == 0) wmax[tid >> 5] = m;
        __syncthreads();
        uint32_t best = kmax32(kmax32(wmax[0],wmax[1]), kmax32(wmax[2],wmax[3]));
        if (lmax == best){
            #pragma unroll
            for (int r=0;r<16;r++){
                if (sk[r][tid] == best){ sk[r][tid] = 0u; break; }
            }
            uint32_t nm = 0u;
            #pragma unroll
            for (int r=0;r<16;r++) nm = kmax32(nm, sk[r][tid]);
            lmax = nm;
        }
        if (tid == 0) g_cand[(size_t)row*NCAND + sel] = 16383 - (int)(best & 16383u);
        __syncthreads();
    }
}

// ---------------- fp32 re-rank of 32 candidates -> top-16 ----------------
__global__ __launch_bounds__(256) void k_refine(){
    int w = threadIdx.x >> 5, lane = threadIdx.x & 31;
    int row = blockIdx.x*8 + w;
    if (row >= NN) return;
    float4 xr = *(const float4*)(g_xn + (size_t)row*DD + lane*4);
    int myidx = g_cand[(size_t)row*NCAND + lane];
    unsigned long long mykey = 0ull;
    #pragma unroll 4
    for (int c=0; c<NCAND; c++){
        int cand = __shfl_sync(0xffffffffu, myidx, c);
        float4 xc = *(const float4*)(g_xn + (size_t)cand*DD + lane*4);
        float p = xr.x*xc.x + xr.y*xc.y + xr.z*xc.z + xr.w*xc.w;
        #pragma unroll
        for (int o=16;o;o>>=1) p += __shfl_xor_sync(0xffffffffu, p, o);
        if (lane == c){
            unsigned u = __float_as_uint(p);
            u = (u & 0x80000000u) ? ~u : (u | 0x80000000u);
            mykey = ((unsigned long long)u << 32) | (unsigned)(~(unsigned)myidx);
        }
    }
    int rank = 0;
    #pragma unroll
    for (int peer=0; peer<32; peer++){
        unsigned long long pk = __shfl_sync(0xffffffffu, mykey, peer);
        rank += (pk > mykey) ? 1 : 0;
    }
    if (rank < 16) g_knn[(size_t)row*16 + rank] = myidx;
}

// ---------------- mult logits: mult[i][j][n] = <x[n,i], wKK[i,j]> + bKK ----
// grid (NP/64, K); gather once per block, NJC=K/16 j-passes
template<int K>
__global__ __launch_bounds__(256) void k_mult(const float* __restrict__ feats,
                                              const int* __restrict__ idx,
                                              int stride, int off0,
                                              const float* __restrict__ wKK,
                                              const float* __restrict__ bKK,
                                              size_t moff){
    constexpr int NJC = K/16;
    __shared__ float4 xsT[32][65];
    __shared__ float  ws[16][128];
    __shared__ float  bsh[K];
    const int tid = threadIdx.x;
    const int i = blockIdx.y;
    const int n0 = blockIdx.x*64;

    if (tid < K) bsh[tid] = bKK[i*K + tid];

    for (int e=tid; e<64*32; e+=256){
        int nn = e>>5, d4 = e&31;
        int n = n0 + nn;
        int src;
        if (idx == nullptr) src = (n < NN) ? g_knn[(size_t)n*16 + i] : 0;
        else                src = (n < NN) ? idx[(size_t)n*stride + off0 + i] : 0;
        xsT[d4][nn] = *(const float4*)(feats + (size_t)src*DD + d4*4);
    }

    const int n  = tid & 63;
    const int jg = tid >> 6;
    float* mout = g_mult + moff;

    #pragma unroll
    for (int jc=0; jc<NJC; jc++){
        // load ws for this group of 16 j
        for (int e=tid; e<16*32; e+=256){
            int jl = e>>5, d4 = e&31;
            float4 v = *(const float4*)(wKK + ((size_t)(i*K + jc*16 + jl))*DD + d4*4);
            *(float4*)&ws[jl][d4*4] = v;
        }
        __syncthreads();

        float acc[4] = {0.f,0.f,0.f,0.f};
        #pragma unroll
        for (int d4=0; d4<32; d4++){
            float4 xv = xsT[d4][n];
            #pragma unroll
            for (int jj=0; jj<4; jj++){
                float4 w = *(const float4*)&ws[jg*4+jj][d4*4];
                acc[jj] += xv.x*w.x + xv.y*w.y + xv.z*w.z + xv.w*w.w;
            }
        }
        #pragma unroll
        for (int jj=0; jj<4; jj++){
            int jglob = jc*16 + jg*4 + jj;
            mout[((size_t)(i*K + jglob))*NP + n0 + n] = acc[jj] + bsh[jglob];
        }
        if (jc+1 < NJC) __syncthreads();
    }
}

// ---------------- coef[j][n] = sum_i wK1[i]*softmax_j(mult[i][:,n]) ---------
template<int K>
__device__ __forceinline__ void coef_body(int n, size_t moff, size_t coff,
                                          const float* __restrict__ wK1){
    const float* mout = g_mult + moff;
    float cacc[K];
    #pragma unroll
    for (int j=0;j<K;j++) cacc[j]=0.f;
    #pragma unroll
    for (int i=0;i<K;i++){
        float v[K];
        float m = -1e30f;
        #pragma unroll
        for (int j=0;j<K;j++){
            v[j] = mout[((size_t)(i*K + j))*NP + n];
            m = fmaxf(m, v[j]);
        }
        float s = 0.f;
        #pragma unroll
        for (int j=0;j<K;j++){ v[j] = __expf(v[j]-m); s += v[j]; }
        float w = wK1[i] / s;
        #pragma unroll
        for (int j=0;j<K;j++) cacc[j] += w * v[j];
    }
    float* cout = g_coef + coff;
    #pragma unroll
    for (int j=0;j<K;j++) cout[(size_t)j*NP + n] = cacc[j];
}

__global__ __launch_bounds__(256) void k_coef_all(const float* __restrict__ wK1_c,
                                                  const float* __restrict__ wK1_n,
                                                  const float* __restrict__ wK1_s){
    int n = blockIdx.x*256 + threadIdx.x;
    if (n >= NN) return;
    const size_t M16 = (size_t)256*NP;
    int br = blockIdx.y;
    if (br < 3)       coef_body<16>(n, (size_t)br*M16, (size_t)br*16*NP, wK1_c);
    else if (br == 3) coef_body<16>(n, 3*M16, (size_t)48*NP, wK1_n);
    else              coef_body<32>(n, 4*M16, (size_t)64*NP, wK1_s);
}

// ---------------- hyper[n][t][:] = sum_j coef[j][n]*feats[idx(n,j)] + bK1 ---
__global__ __launch_bounds__(256) void k_hyper_all(const float* __restrict__ feats,
                                                   const int* __restrict__ cidx,
                                                   const int* __restrict__ sidx,
                                                   const float* __restrict__ bK1_c,
                                                   const float* __restrict__ bK1_n,
                                                   const float* __restrict__ bK1_s){
    int w = threadIdx.x >> 5, lane = threadIdx.x & 31;
    int n = blockIdx.x*8 + w;
    if (n >= NN) return;
    int t = blockIdx.y;
    const int* idx; int stride, off0, K; const float* bK1; size_t coff;
    if (t < 3){ idx = cidx; stride = 48; off0 = t*16; K = 16; bK1 = bK1_c; coff = (size_t)t*16*NP; }
    else if (t == 3){ idx = g_knn; stride = 16; off0 = 0; K = 16; bK1 = bK1_n; coff = (size_t)48*NP; }
    else { idx = sidx; stride = 32; off0 = 0; K = 32; bK1 = bK1_s; coff = (size_t)64*NP; }

    const float* coef = g_coef + coff;
    float4 acc = make_float4(0.f,0.f,0.f,0.f);
    #pragma unroll 4
    for (int j=0;j<K;j++){
        float c = __ldg(&coef[(size_t)j*NP + n]);
        int src = idx[(size_t)n*stride + off0 + j];
        float4 f = *(const float4*)(feats + (size_t)src*DD + lane*4);
        acc.x += c*f.x; acc.y += c*f.y; acc.z += c*f.z; acc.w += c*f.w;
    }
    float b = bK1[0];
    acc.x += b; acc.y += b; acc.z += b; acc.w += b;
    *(float4*)(g_hyper + ((size_t)n*5 + t)*DD + lane*4) = acc;
}

// ---------------- EdgeConv attention + final FC ----------------
__global__ __launch_bounds__(128) void k_final(const float* __restrict__ ec_w1,
                                               const float* __restrict__ ec_b1,
                                               const float* __restrict__ ec_w2,
                                               const float* __restrict__ ec_b2,
                                               const float* __restrict__ fc_w,
                                               const float* __restrict__ fc_b,
                                               float* __restrict__ out){
    extern __shared__ float fsm[];
    float* fcw  = fsm;
    float* w1s  = fsm + 16384;
    float* xs   = fsm + 16384 + 4096;
    float* aggs = xs + 4*640;
    int tid = threadIdx.x;
    for (int e=tid; e<16384/4; e+=128)
        *(float4*)&fcw[e*4] = *(const float4*)&fc_w[e*4];
    for (int e=tid; e<4096/4; e+=128)
        *(float4*)&w1s[e*4] = *(const float4*)&ec_w1[e*4];
    __syncthreads();

    int w = tid >> 5, lane = tid & 31;
    int n = blockIdx.x*4 + w;

    float4 xr[5];
    #pragma unroll
    for (int t=0;t<5;t++){
        xr[t] = *(const float4*)(g_hyper + ((size_t)n*5 + t)*DD + lane*4);
        *(float4*)&xs[w*640 + t*128 + lane*4] = xr[t];
    }
    __syncwarp();

    float w2v = ec_w2[lane];
    float b1v = ec_b1[lane];
    float sc[5];
    #pragma unroll
    for (int t=0;t<5;t++){
        float h = b1v;
        #pragma unroll 4
        for (int d=0; d<DD; d++)
            h += xs[w*640 + t*128 + d] * w1s[d*32 + lane];
        h = fmaxf(h, 0.f);
        float p = h * w2v;
        #pragma unroll
        for (int o=16;o;o>>=1) p += __shfl_xor_sync(0xffffffffu, p, o);
        sc[t] = p;
    }
    float b2 = ec_b2[0];
    float m = -1e30f;
    #pragma unroll
    for (int t=0;t<5;t++){ sc[t] += b2; m = fmaxf(m, sc[t]); }
    float s = 0.f;
    #pragma unroll
    for (int t=0;t<5;t++){ sc[t] = __expf(sc[t]-m); s += sc[t]; }
    float inv = 1.f/s;
    #pragma unroll
    for (int t=0;t<5;t++) sc[t] *= inv;

    float4 a = make_float4(0.f,0.f,0.f,0.f);
    #pragma unroll
    for (int t=0;t<5;t++){
        a.x += sc[t]*xr[t].x; a.y += sc[t]*xr[t].y;
        a.z += sc[t]*xr[t].z; a.w += sc[t]*xr[t].w;
    }
    *(float4*)&aggs[w*128 + lane*4] = a;
    __syncwarp();

    float4 o = *(const float4*)&fc_b[lane*4];
    #pragma unroll 4
    for (int d=0; d<DD; d++){
        float av = aggs[w*128 + d];
        float4 fw = *(const float4*)&fcw[d*128 + lane*4];
        o.x += av*fw.x; o.y += av*fw.y; o.z += av*fw.z; o.w += av*fw.w;
    }
    o.x = fmaxf(o.x,0.f); o.y = fmaxf(o.y,0.f);
    o.z = fmaxf(o.z,0.f); o.w = fmaxf(o.w,0.f);
    *(float4*)(out + (size_t)n*DD + lane*4) = o;
}

// ---------------- launch ----------------
extern "C" void kernel_launch(void* const* d_in, const int* in_sizes, int n_in,
                              void* d_out, int out_size){
    const float* feats  = (const float*)d_in[1];
    const int*   cidx   = (const int*)d_in[2];
    const int*   sidx   = (const int*)d_in[3];
    const float* wKK_c  = (const float*)d_in[5];
    const float* bKK_c  = (const float*)d_in[6];
    const float* wK1_c  = (const float*)d_in[7];
    const float* bK1_c  = (const float*)d_in[8];
    const float* wKK_n  = (const float*)d_in[9];
    const float* bKK_n  = (const float*)d_in[10];
    const float* wK1_n  = (const float*)d_in[11];
    const float* bK1_n  = (const float*)d_in[12];
    const float* wKK_s  = (const float*)d_in[13];
    const float* bKK_s  = (const float*)d_in[14];
    const float* wK1_s  = (const float*)d_in[15];
    const float* bK1_s  = (const float*)d_in[16];
    const float* ec_w1  = (const float*)d_in[17];
    const float* ec_b1  = (const float*)d_in[18];
    const float* ec_w2  = (const float*)d_in[19];
    const float* ec_b2  = (const float*)d_in[20];
    const float* fc_w   = (const float*)d_in[21];
    const float* fc_b   = (const float*)d_in[22];
    float* out = (float*)d_out;

    cudaFuncSetAttribute(k_simT, cudaFuncAttributeMaxDynamicSharedMemorySize, SIM_SMEM);
    cudaFuncSetAttribute(k_final, cudaFuncAttributeMaxDynamicSharedMemorySize, 94208);

    k_norm<<<NPG/8, 256>>>(feats);
    k_simT<<<dim3(NPG/128, NPG/128), 256, SIM_SMEM>>>();
    k_topk<<<NN, 128>>>();
    k_refine<<<(NN+7)/8, 256>>>();

    const size_t M16 = (size_t)256*NP;
    for (int c=0;c<3;c++)
        k_mult<16><<<dim3(NP/64,16),256>>>(feats, cidx, 48, c*16, wKK_c, bKK_c, (size_t)c*M16);
    k_mult<16><<<dim3(NP/64,16),256>>>(feats, nullptr, 16, 0, wKK_n, bKK_n, 3*M16);
    k_mult<32><<<dim3(NP/64,32),256>>>(feats, sidx, 32, 0, wKK_s, bKK_s, 4*M16);

    int cb = (NN + 255)/256;
    k_coef_all<<<dim3(cb,5),256>>>(wK1_c, wK1_n, wK1_s);

    k_hyper_all<<<dim3(NN/8,5),256>>>(feats, cidx, sidx, bK1_c, bK1_n, bK1_s);

    k_final<<<NN/4, 128, 94208>>>(ec_w1, ec_b1, ec_w2, ec_b2, fc_w, fc_b, out);
}